// round 9
// baseline (speedup 1.0000x reference)
#include <cuda_runtime.h>
#include <cuda_fp16.h>
#include <cstdint>
#include <cstddef>

#define BB   8
#define NN   2048
#define FIN  256
#define FOUT 64
#define ALPHA 0.2f
#define SPLIT 4
#define ROWS_TOT (BB * NN)

// ---------------- scratch (device globals: allocation-free) ----------------
__device__ float2 g_thR[ROWS_TOT];                   // (-sb_i, exp((a-1)*sb_i))
__device__ float4 g_EEd[ROWS_TOT];                   // (exp(d_j), exp(a*d_j), d_j, 0)
__device__ unsigned short g_hhT[BB * FOUT * NN];     // fp16 hi, [b][feat][j]
__device__ unsigned short g_hlT[BB * FOUT * NN];     // fp16 lo residual
__device__ float g_pacc[SPLIT * ROWS_TOT * FOUT];    // 16 MB split-K partials
__device__ float g_pl[SPLIT * ROWS_TOT];
__device__ int   g_cnt[16 * BB];                     // split-K arrival counters

// ---------------- helpers ----------------
static __device__ __forceinline__ uint32_t cvt2h(float lo, float hi) {
    uint32_t d;
    asm("cvt.rn.f16x2.f32 %0, %1, %2;" : "=r"(d) : "f"(hi), "f"(lo));
    return d;
}
static __device__ __forceinline__ float h_lo(uint32_t w) {
    return __half2float(__ushort_as_half((unsigned short)(w & 0xffffu)));
}
static __device__ __forceinline__ float h_hi(uint32_t w) {
    return __half2float(__ushort_as_half((unsigned short)(w >> 16)));
}

static __device__ __forceinline__ void mma16816h(float* c, const uint32_t* a,
                                                 uint32_t b0, uint32_t b1) {
    asm volatile(
        "mma.sync.aligned.m16n8k16.row.col.f32.f16.f16.f32 "
        "{%0,%1,%2,%3}, {%4,%5,%6,%7}, {%8,%9}, {%0,%1,%2,%3};"
        : "+f"(c[0]), "+f"(c[1]), "+f"(c[2]), "+f"(c[3])
        : "r"(a[0]), "r"(a[1]), "r"(a[2]), "r"(a[3]), "r"(b0), "r"(b1));
}

// ============================================================================
// Kernel 1: h = x @ W + b_W via mma.sync fp16-split (3-term).
// 128 threads, 64 rows/CTA, grid 256 (full SM coverage, 3 CTAs/SM).
// Epilogue buffer ALIASES the W-prepack smem (W dead after mainloop).
// Also zeroes the split-K arrival counters for k_attn3.
// ============================================================================
#define LIN_SW_BYTES 32768
#define LIN_HB_STRIDE 68
#define LIN_SMEM (2 * LIN_SW_BYTES)     // 64 KB; hbuf aliases the first 17.4 KB

__global__ __launch_bounds__(128, 3) void k_linear(
    const float* __restrict__ x, const float* __restrict__ W,
    const float* __restrict__ bW, const float* __restrict__ a_src,
    const float* __restrict__ a_dst, const float* __restrict__ a_b)
{
    extern __shared__ __align__(16) unsigned char lsm[];
    uint32_t* WH32 = (uint32_t*)lsm;
    uint32_t* WL32 = (uint32_t*)(lsm + LIN_SW_BYTES);
    float*    hbuf = (float*)lsm;                     // alias (used post-mainloop)

    const int t    = threadIdx.x;
    const int w    = t >> 5;
    const int lane = t & 31;
    const int q    = lane & 3;
    const int r    = lane >> 2;
    const int i0   = blockIdx.x * 64;
    const float ab = a_b[0];

    if (blockIdx.x == 0) g_cnt[t] = 0;   // reset split-K counters (128 of them)

    // ---- prepack W into fragment-order fp16 hi/lo ----
#pragma unroll
    for (int i = 0; i < 64; i++) {
        int u    = t + 128 * i;
        int half = u & 1;
        int qq   = (u >> 1) & 3;
        int n    = (u >> 3) & 63;
        int ks   = u >> 9;
        int k0   = ks * 16 + half * 8 + 2 * qq;
        float w0 = W[(size_t)k0 * FOUT + n];
        float w1 = W[(size_t)(k0 + 1) * FOUT + n];
        uint32_t hi = cvt2h(w0, w1);
        WH32[u] = hi;
        WL32[u] = cvt2h(w0 - h_lo(hi), w1 - h_hi(hi));
    }
    __syncthreads();

    const float* xA = x + (size_t)(i0 + w * 16 + r) * FIN;
    const float* xB = xA + (size_t)8 * FIN;

    float c[8][4];
#pragma unroll
    for (int n = 0; n < 8; n++)
#pragma unroll
        for (int k = 0; k < 4; k++) c[n][k] = 0.0f;

    // x register double-buffer
    float2 xb[2][4];
    xb[0][0] = *(const float2*)(xA + 2 * q);
    xb[0][1] = *(const float2*)(xB + 2 * q);
    xb[0][2] = *(const float2*)(xA + 8 + 2 * q);
    xb[0][3] = *(const float2*)(xB + 8 + 2 * q);

#pragma unroll
    for (int ks = 0; ks < 16; ks++) {
        const int cur = ks & 1;
        if (ks + 1 < 16) {
            const int kb = (ks + 1) * 16;
            xb[cur ^ 1][0] = *(const float2*)(xA + kb + 2 * q);
            xb[cur ^ 1][1] = *(const float2*)(xB + kb + 2 * q);
            xb[cur ^ 1][2] = *(const float2*)(xA + kb + 8 + 2 * q);
            xb[cur ^ 1][3] = *(const float2*)(xB + kb + 8 + 2 * q);
        }

        uint32_t ah[4], al[4];
#pragma unroll
        for (int e = 0; e < 4; e++) {
            float2 xv = xb[cur][e];
            ah[e] = cvt2h(xv.x, xv.y);
            al[e] = cvt2h(xv.x - h_lo(ah[e]), xv.y - h_hi(ah[e]));
        }

#pragma unroll
        for (int nt = 0; nt < 8; nt++) {
            int slot = (ks * 64 + nt * 8 + r) * 4 + q;
            uint2 bh = *(const uint2*)&WH32[slot * 2];
            uint2 bl = *(const uint2*)&WL32[slot * 2];
            mma16816h(c[nt], ah, bh.x, bh.y);
            mma16816h(c[nt], ah, bl.x, bl.y);
            mma16816h(c[nt], al, bh.x, bh.y);
        }
    }

    // ---- stash c to (aliased) smem — all W reads are done ----
    __syncthreads();
    {
        float* hbA = hbuf + (w * 16 + r) * LIN_HB_STRIDE;
        float* hbB = hbA + 8 * LIN_HB_STRIDE;
#pragma unroll
        for (int nt = 0; nt < 8; nt++) {
            *(float2*)(hbA + nt * 8 + 2 * q) = make_float2(c[nt][0], c[nt][1]);
            *(float2*)(hbB + nt * 8 + 2 * q) = make_float2(c[nt][2], c[nt][3]);
        }
    }
    __syncthreads();

    // ---- epilogue: fc = feat group (0..15), rw -> 8 rows each ----
    const int fc = t & 15;
    const int rw = t >> 4;
    float4 bw4 = *(const float4*)&bW[fc * 4];
    float4 as4 = *(const float4*)&a_src[fc * 4];
    float4 ad4 = *(const float4*)&a_dst[fc * 4];

    float hv[8][4];
    float sp[8], dp[8];
#pragma unroll
    for (int e = 0; e < 8; e++) {
        float4 v = *(const float4*)&hbuf[(rw * 8 + e) * LIN_HB_STRIDE + fc * 4];
        hv[e][0] = v.x + bw4.x; hv[e][1] = v.y + bw4.y;
        hv[e][2] = v.z + bw4.z; hv[e][3] = v.w + bw4.w;
        sp[e] = hv[e][0] * as4.x + hv[e][1] * as4.y + hv[e][2] * as4.z + hv[e][3] * as4.w;
        dp[e] = hv[e][0] * ad4.x + hv[e][1] * ad4.y + hv[e][2] * ad4.z + hv[e][3] * ad4.w;
    }
#pragma unroll
    for (int o = 1; o < 16; o <<= 1) {
#pragma unroll
        for (int e = 0; e < 8; e++) {
            sp[e] += __shfl_xor_sync(0xffffffffu, sp[e], o);
            dp[e] += __shfl_xor_sync(0xffffffffu, dp[e], o);
        }
    }
    if (fc == 0) {
#pragma unroll
        for (int e = 0; e < 8; e++) {
            int row = i0 + rw * 8 + e;
            float sb = sp[e] + ab;
            g_thR[row] = make_float2(-sb, expf((ALPHA - 1.0f) * sb));
            g_EEd[row] = make_float4(expf(dp[e]), expf(ALPHA * dp[e]), dp[e], 0.0f);
        }
    }

    // ---- transposed fp16-split stores: [b][feat][j] ----
    const int    jb    = (i0 & (NN - 1)) + rw * 8;
    const size_t plane = (size_t)(i0 >> 11) * FOUT;
#pragma unroll
    for (int ff = 0; ff < 4; ff++) {
        int f = fc * 4 + ff;
        uint32_t hh[4], ll[4];
#pragma unroll
        for (int p2 = 0; p2 < 4; p2++) {
            float v0 = hv[p2 * 2][ff], v1 = hv[p2 * 2 + 1][ff];
            uint32_t h = cvt2h(v0, v1);
            hh[p2] = h;
            ll[p2] = cvt2h(v0 - h_lo(h), v1 - h_hi(h));
        }
        size_t idx = (plane + f) * NN + jb;
        *(uint2*)&g_hhT[idx]     = make_uint2(hh[0], hh[1]);
        *(uint2*)&g_hhT[idx + 4] = make_uint2(hh[2], hh[3]);
        *(uint2*)&g_hlT[idx]     = make_uint2(ll[0], ll[1]);
        *(uint2*)&g_hlT[idx + 4] = make_uint2(ll[2], ll[3]);
    }
}

// ============================================================================
// Kernel 2: split-K masked softmax-weight P@h via mma.sync fp16.
// Last-arriving z-CTA per (i-tile, b) fuses the split-K reduction + ELU + store.
// ============================================================================
#define NC (NN / 32)
#define BSTRIDE 80

__global__ __launch_bounds__(256, 2) void k_attn3(
    const int* __restrict__ adj, float* __restrict__ out)
{
    __shared__ __align__(16) uint8_t sBH[2][FOUT * BSTRIDE];
    __shared__ __align__(16) uint8_t sBL[2][FOUT * BSTRIDE];
    __shared__ float4 sEE[2][32];
    __shared__ int s_last;

    const int t    = threadIdx.x;
    const int wid  = t >> 5;
    const int lane = t & 31;
    const int q    = lane & 3;
    const int r    = lane >> 2;
    const int b    = blockIdx.y;
    const int i0   = blockIdx.x * 128;
    const int z    = blockIdx.z;
    const int ch0  = z * (NC / SPLIT);
    const int ch1  = ch0 + (NC / SPLIT);

    const int iA = i0 + wid * 16 + r;
    const int iB = iA + 8;
    const size_t bNN = (size_t)b * NN;

    const float2 tA = g_thR[bNN + iA];
    const float2 tB = g_thR[bNN + iB];
    const int* aA = adj + bNN * NN + (size_t)iA * NN + 2 * q;
    const int* aB = aA + 8 * NN;

    float c[8][4];
#pragma unroll
    for (int n = 0; n < 8; n++)
#pragma unroll
        for (int k = 0; k < 4; k++) c[n][k] = 0.0f;
    float laccA = 0.0f, laccB = 0.0f;

    const int feat = t >> 2;
    const int jq   = (t & 3) * 8;
    const unsigned short* hhp = g_hhT + ((size_t)b * FOUT + feat) * NN + jq;
    const unsigned short* hlp = g_hlT + ((size_t)b * FOUT + feat) * NN + jq;
    const uint32_t sOff = (uint32_t)feat * BSTRIDE + (uint32_t)jq * 2;

    // prologue: stage first chunk B/EE, preload first chunk adj into regs
    *(uint4*)&sBH[0][sOff] = *(const uint4*)(hhp + ch0 * 32);
    *(uint4*)&sBL[0][sOff] = *(const uint4*)(hlp + ch0 * 32);
    if (t < 32) sEE[0][t] = g_EEd[bNN + ch0 * 32 + t];

    int2 mC[8];
#pragma unroll
    for (int kk = 0; kk < 2; kk++) {
        const int jo = ch0 * 32 + kk * 16;
        mC[kk * 4 + 0] = *(const int2*)(aA + jo);
        mC[kk * 4 + 1] = *(const int2*)(aA + jo + 8);
        mC[kk * 4 + 2] = *(const int2*)(aB + jo);
        mC[kk * 4 + 3] = *(const int2*)(aB + jo + 8);
    }
    __syncthreads();

    const uint32_t tb = (uint32_t)r * BSTRIDE + (uint32_t)q * 4;

    uint4 pf_h, pf_l; float4 pf_e;
#pragma unroll 1
    for (int ch = ch0; ch < ch1; ch++) {
        const int s   = ch & 1;
        const int j0c = ch * 32;

        int2 mN[8];
        if (ch + 1 < ch1) {
            pf_h = *(const uint4*)(hhp + j0c + 32);
            pf_l = *(const uint4*)(hlp + j0c + 32);
            if (t < 32) pf_e = g_EEd[bNN + j0c + 32 + t];
#pragma unroll
            for (int kk = 0; kk < 2; kk++) {
                const int jo = j0c + 32 + kk * 16;
                mN[kk * 4 + 0] = *(const int2*)(aA + jo);
                mN[kk * 4 + 1] = *(const int2*)(aA + jo + 8);
                mN[kk * 4 + 2] = *(const int2*)(aB + jo);
                mN[kk * 4 + 3] = *(const int2*)(aB + jo + 8);
            }
        }

        // ---- A fragments from buffered adj + sEE ----
        uint32_t ah[2][4];
#pragma unroll
        for (int kk = 0; kk < 2; kk++) {
            const int jl = kk * 16 + 2 * q;
            float4 eA0 = sEE[s][jl];
            float4 eA1 = sEE[s][jl + 1];
            float4 eB0 = sEE[s][jl + 8];
            float4 eB1 = sEE[s][jl + 9];
            int2 mAa = mC[kk * 4 + 0];
            int2 mAb = mC[kk * 4 + 1];
            int2 mBa = mC[kk * 4 + 2];
            int2 mBb = mC[kk * 4 + 3];

            float pAa0 = (eA0.z >= tA.x) ? eA0.x : tA.y * eA0.y; if (mAa.x == 0) pAa0 = 0.0f;
            float pAa1 = (eA1.z >= tA.x) ? eA1.x : tA.y * eA1.y; if (mAa.y == 0) pAa1 = 0.0f;
            float pAb0 = (eB0.z >= tA.x) ? eB0.x : tA.y * eB0.y; if (mAb.x == 0) pAb0 = 0.0f;
            float pAb1 = (eB1.z >= tA.x) ? eB1.x : tA.y * eB1.y; if (mAb.y == 0) pAb1 = 0.0f;
            float pBa0 = (eA0.z >= tB.x) ? eA0.x : tB.y * eA0.y; if (mBa.x == 0) pBa0 = 0.0f;
            float pBa1 = (eA1.z >= tB.x) ? eA1.x : tB.y * eA1.y; if (mBa.y == 0) pBa1 = 0.0f;
            float pBb0 = (eB0.z >= tB.x) ? eB0.x : tB.y * eB0.y; if (mBb.x == 0) pBb0 = 0.0f;
            float pBb1 = (eB1.z >= tB.x) ? eB1.x : tB.y * eB1.y; if (mBb.y == 0) pBb1 = 0.0f;

            laccA += (pAa0 + pAa1) + (pAb0 + pAb1);
            laccB += (pBa0 + pBa1) + (pBb0 + pBb1);

            ah[kk][0] = cvt2h(pAa0, pAa1);
            ah[kk][1] = cvt2h(pBa0, pBa1);
            ah[kk][2] = cvt2h(pAb0, pAb1);
            ah[kk][3] = cvt2h(pBb0, pBb1);
        }

        // ---- mma: 8 n-tiles x 2 k-steps x 2 ----
#pragma unroll
        for (int n = 0; n < 8; n++) {
#pragma unroll
            for (int kk = 0; kk < 2; kk++) {
                uint32_t off = (uint32_t)n * (8 * BSTRIDE) + (uint32_t)kk * 32 + tb;
                uint32_t bh0 = *(const uint32_t*)&sBH[s][off];
                uint32_t bh1 = *(const uint32_t*)&sBH[s][off + 16];
                uint32_t bl0 = *(const uint32_t*)&sBL[s][off];
                uint32_t bl1 = *(const uint32_t*)&sBL[s][off + 16];
                mma16816h(c[n], ah[kk], bh0, bh1);
                mma16816h(c[n], ah[kk], bl0, bl1);
            }
        }

        if (ch + 1 < ch1) {
            *(uint4*)&sBH[s ^ 1][sOff] = pf_h;
            *(uint4*)&sBL[s ^ 1][sOff] = pf_l;
            if (t < 32) sEE[s ^ 1][t] = pf_e;
#pragma unroll
            for (int u = 0; u < 8; u++) mC[u] = mN[u];
        }
        __syncthreads();
    }

    // ---- write split-K partials ----
    laccA += __shfl_xor_sync(0xffffffffu, laccA, 1);
    laccA += __shfl_xor_sync(0xffffffffu, laccA, 2);
    laccB += __shfl_xor_sync(0xffffffffu, laccB, 1);
    laccB += __shfl_xor_sync(0xffffffffu, laccB, 2);

    float* pa = g_pacc + (size_t)z * ((size_t)ROWS_TOT * FOUT);
    float* opA = pa + (bNN + iA) * FOUT + 2 * q;
    float* opB = pa + (bNN + iB) * FOUT + 2 * q;
#pragma unroll
    for (int n = 0; n < 8; n++) {
        *(float2*)(opA + n * 8) = make_float2(c[n][0], c[n][1]);
        *(float2*)(opB + n * 8) = make_float2(c[n][2], c[n][3]);
    }
    if (q == 0) {
        g_pl[(size_t)z * ROWS_TOT + bNN + iA] = laccA;
        g_pl[(size_t)z * ROWS_TOT + bNN + iB] = laccB;
    }

    // ---- fused split-K finalize: last-arriving CTA reduces + ELU + stores ----
    __threadfence();
    if (t == 0) {
        int old = atomicAdd(&g_cnt[blockIdx.x * BB + b], 1);
        s_last = (old == SPLIT - 1) ? 1 : 0;
    }
    __syncthreads();
    if (s_last) {
        __threadfence();
        const size_t PS = (size_t)ROWS_TOT * FOUT;
#pragma unroll 2
        for (int u = t; u < 128 * 16; u += 256) {
            const int row_l = u >> 4;
            const int fg    = (u & 15) << 2;
            const size_t rowg = bNN + i0 + row_l;
            const size_t o    = rowg * FOUT + fg;

            float l = 0.0f;
            float4 a = make_float4(0.0f, 0.0f, 0.0f, 0.0f);
#pragma unroll
            for (int zz = 0; zz < SPLIT; zz++) {
                l += g_pl[(size_t)zz * ROWS_TOT + rowg];
                float4 p = *(const float4*)&g_pacc[(size_t)zz * PS + o];
                a.x += p.x; a.y += p.y; a.z += p.z; a.w += p.w;
            }
            const float li = 1.0f / l;
            float v0 = a.x * li, v1 = a.y * li, v2 = a.z * li, v3 = a.w * li;
            v0 = v0 > 0.0f ? v0 : expm1f(v0);
            v1 = v1 > 0.0f ? v1 : expm1f(v1);
            v2 = v2 > 0.0f ? v2 : expm1f(v2);
            v3 = v3 > 0.0f ? v3 : expm1f(v3);
            *(float4*)&out[o] = make_float4(v0, v1, v2, v3);
        }
    }
}

// ============================================================================
extern "C" void kernel_launch(void* const* d_in, const int* in_sizes, int n_in,
                              void* d_out, int out_size)
{
    const float* x     = (const float*)d_in[0];
    const int*   adj   = (const int*)d_in[1];
    const float* W     = (const float*)d_in[2];
    const float* bW    = (const float*)d_in[3];
    const float* a_src = (const float*)d_in[4];
    const float* a_dst = (const float*)d_in[5];
    const float* a_b   = (const float*)d_in[6];
    float* out = (float*)d_out;
    (void)in_sizes; (void)n_in; (void)out_size;

    cudaFuncSetAttribute(k_linear, cudaFuncAttributeMaxDynamicSharedMemorySize,
                         LIN_SMEM);

    k_linear<<<ROWS_TOT / 64, 128, LIN_SMEM>>>(x, W, bW, a_src, a_dst, a_b);

    dim3 grid(NN / 128, BB, SPLIT);
    k_attn3<<<grid, 256>>>(adj, out);
}

// round 10
// speedup vs baseline: 1.1092x; 1.1092x over previous
#include <cuda_runtime.h>
#include <cuda_fp16.h>
#include <cstdint>
#include <cstddef>

#define BB   8
#define NN   2048
#define FIN  256
#define FOUT 64
#define ALPHA 0.2f
#define SPLIT 4
#define ROWS_TOT (BB * NN)

// ---------------- scratch (device globals: allocation-free) ----------------
__device__ float2 g_thR[ROWS_TOT];                   // (-sb_i, exp((a-1)*sb_i))
__device__ float4 g_EEd[ROWS_TOT];                   // (exp(d_j), exp(a*d_j), d_j, 0)
// h transposed fp16 hi/lo, [b][feat][j], j stored 32-chunk INTERLEAVED:
//   pos(j) = (j&~31) + q*8 + kk*4 + half*2 + elem
//   kk=(j>>4)&1, half=(j>>3)&1, q=(j>>1)&3, elem=j&1
__device__ unsigned short g_hhT[BB * FOUT * NN];
__device__ unsigned short g_hlT[BB * FOUT * NN];
__device__ float g_pacc[SPLIT * ROWS_TOT * FOUT];    // 16 MB split-K partials
__device__ float g_pl[SPLIT * ROWS_TOT];

// ---------------- helpers ----------------
static __device__ __forceinline__ uint32_t cvt2h(float lo, float hi) {
    uint32_t d;
    asm("cvt.rn.f16x2.f32 %0, %1, %2;" : "=r"(d) : "f"(hi), "f"(lo));
    return d;
}
static __device__ __forceinline__ float h_lo(uint32_t w) {
    return __half2float(__ushort_as_half((unsigned short)(w & 0xffffu)));
}
static __device__ __forceinline__ float h_hi(uint32_t w) {
    return __half2float(__ushort_as_half((unsigned short)(w >> 16)));
}

static __device__ __forceinline__ void mma16816h(float* c, const uint32_t* a,
                                                 uint32_t b0, uint32_t b1) {
    asm volatile(
        "mma.sync.aligned.m16n8k16.row.col.f32.f16.f16.f32 "
        "{%0,%1,%2,%3}, {%4,%5,%6,%7}, {%8,%9}, {%0,%1,%2,%3};"
        : "+f"(c[0]), "+f"(c[1]), "+f"(c[2]), "+f"(c[3])
        : "r"(a[0]), "r"(a[1]), "r"(a[2]), "r"(a[3]), "r"(b0), "r"(b1));
}

// ============================================================================
// Kernel 1: h = x @ W + b_W via mma.sync fp16-split (3-term).
// 128 threads, 64 rows/CTA, grid 256. Epilogue buffer aliases W-prepack smem.
// ============================================================================
#define LIN_SW_BYTES 32768
#define LIN_HB_STRIDE 68
#define LIN_SMEM (2 * LIN_SW_BYTES)

__global__ __launch_bounds__(128, 3) void k_linear(
    const float* __restrict__ x, const float* __restrict__ W,
    const float* __restrict__ bW, const float* __restrict__ a_src,
    const float* __restrict__ a_dst, const float* __restrict__ a_b)
{
    extern __shared__ __align__(16) unsigned char lsm[];
    uint32_t* WH32 = (uint32_t*)lsm;
    uint32_t* WL32 = (uint32_t*)(lsm + LIN_SW_BYTES);
    float*    hbuf = (float*)lsm;                     // alias (post-mainloop)

    const int t    = threadIdx.x;
    const int w    = t >> 5;
    const int lane = t & 31;
    const int q    = lane & 3;
    const int r    = lane >> 2;
    const int i0   = blockIdx.x * 64;
    const float ab = a_b[0];

    // ---- prepack W into fragment-order fp16 hi/lo ----
#pragma unroll
    for (int i = 0; i < 64; i++) {
        int u    = t + 128 * i;
        int half = u & 1;
        int qq   = (u >> 1) & 3;
        int n    = (u >> 3) & 63;
        int ks   = u >> 9;
        int k0   = ks * 16 + half * 8 + 2 * qq;
        float w0 = W[(size_t)k0 * FOUT + n];
        float w1 = W[(size_t)(k0 + 1) * FOUT + n];
        uint32_t hi = cvt2h(w0, w1);
        WH32[u] = hi;
        WL32[u] = cvt2h(w0 - h_lo(hi), w1 - h_hi(hi));
    }
    __syncthreads();

    const float* xA = x + (size_t)(i0 + w * 16 + r) * FIN;
    const float* xB = xA + (size_t)8 * FIN;

    float c[8][4];
#pragma unroll
    for (int n = 0; n < 8; n++)
#pragma unroll
        for (int k = 0; k < 4; k++) c[n][k] = 0.0f;

    float2 xb[2][4];
    xb[0][0] = *(const float2*)(xA + 2 * q);
    xb[0][1] = *(const float2*)(xB + 2 * q);
    xb[0][2] = *(const float2*)(xA + 8 + 2 * q);
    xb[0][3] = *(const float2*)(xB + 8 + 2 * q);

#pragma unroll
    for (int ks = 0; ks < 16; ks++) {
        const int cur = ks & 1;
        if (ks + 1 < 16) {
            const int kb = (ks + 1) * 16;
            xb[cur ^ 1][0] = *(const float2*)(xA + kb + 2 * q);
            xb[cur ^ 1][1] = *(const float2*)(xB + kb + 2 * q);
            xb[cur ^ 1][2] = *(const float2*)(xA + kb + 8 + 2 * q);
            xb[cur ^ 1][3] = *(const float2*)(xB + kb + 8 + 2 * q);
        }

        uint32_t ah[4], al[4];
#pragma unroll
        for (int e = 0; e < 4; e++) {
            float2 xv = xb[cur][e];
            ah[e] = cvt2h(xv.x, xv.y);
            al[e] = cvt2h(xv.x - h_lo(ah[e]), xv.y - h_hi(ah[e]));
        }

#pragma unroll
        for (int nt = 0; nt < 8; nt++) {
            int slot = (ks * 64 + nt * 8 + r) * 4 + q;
            uint2 bh = *(const uint2*)&WH32[slot * 2];
            uint2 bl = *(const uint2*)&WL32[slot * 2];
            mma16816h(c[nt], ah, bh.x, bh.y);
            mma16816h(c[nt], ah, bl.x, bl.y);
            mma16816h(c[nt], al, bh.x, bh.y);
        }
    }

    // ---- stash c to (aliased) smem ----
    __syncthreads();
    {
        float* hbA = hbuf + (w * 16 + r) * LIN_HB_STRIDE;
        float* hbB = hbA + 8 * LIN_HB_STRIDE;
#pragma unroll
        for (int nt = 0; nt < 8; nt++) {
            *(float2*)(hbA + nt * 8 + 2 * q) = make_float2(c[nt][0], c[nt][1]);
            *(float2*)(hbB + nt * 8 + 2 * q) = make_float2(c[nt][2], c[nt][3]);
        }
    }
    __syncthreads();

    // ---- epilogue ----
    const int fc = t & 15;
    const int rw = t >> 4;
    float4 bw4 = *(const float4*)&bW[fc * 4];
    float4 as4 = *(const float4*)&a_src[fc * 4];
    float4 ad4 = *(const float4*)&a_dst[fc * 4];

    float hv[8][4];
    float sp[8], dp[8];
#pragma unroll
    for (int e = 0; e < 8; e++) {
        float4 v = *(const float4*)&hbuf[(rw * 8 + e) * LIN_HB_STRIDE + fc * 4];
        hv[e][0] = v.x + bw4.x; hv[e][1] = v.y + bw4.y;
        hv[e][2] = v.z + bw4.z; hv[e][3] = v.w + bw4.w;
        sp[e] = hv[e][0] * as4.x + hv[e][1] * as4.y + hv[e][2] * as4.z + hv[e][3] * as4.w;
        dp[e] = hv[e][0] * ad4.x + hv[e][1] * ad4.y + hv[e][2] * ad4.z + hv[e][3] * ad4.w;
    }
#pragma unroll
    for (int o = 1; o < 16; o <<= 1) {
#pragma unroll
        for (int e = 0; e < 8; e++) {
            sp[e] += __shfl_xor_sync(0xffffffffu, sp[e], o);
            dp[e] += __shfl_xor_sync(0xffffffffu, dp[e], o);
        }
    }
    if (fc == 0) {
#pragma unroll
        for (int e = 0; e < 8; e++) {
            int row = i0 + rw * 8 + e;
            float sb = sp[e] + ab;
            g_thR[row] = make_float2(-sb, expf((ALPHA - 1.0f) * sb));
            g_EEd[row] = make_float4(expf(dp[e]), expf(ALPHA * dp[e]), dp[e], 0.0f);
        }
    }

    // ---- transposed fp16-split stores, 32-chunk INTERLEAVED order ----
    // run jb..jb+7 (jb mult of 8): kk, half const; pair p2 -> q=p2.
    const int    jb    = (i0 & (NN - 1)) + rw * 8;
    const size_t plane = (size_t)(i0 >> 11) * FOUT;
    const int    ibase = (jb & ~31) + (((jb >> 4) & 1) << 2) + (((jb >> 3) & 1) << 1);
#pragma unroll
    for (int ff = 0; ff < 4; ff++) {
        int f = fc * 4 + ff;
        size_t rowb = (plane + f) * NN + ibase;
#pragma unroll
        for (int p2 = 0; p2 < 4; p2++) {
            float v0 = hv[p2 * 2][ff], v1 = hv[p2 * 2 + 1][ff];
            uint32_t h = cvt2h(v0, v1);
            uint32_t l = cvt2h(v0 - h_lo(h), v1 - h_hi(h));
            *(uint32_t*)&g_hhT[rowb + p2 * 8] = h;
            *(uint32_t*)&g_hlT[rowb + p2 * 8] = l;
        }
    }
}

// ============================================================================
// Kernel 2: split-K masked softmax-weight P@h via mma.sync fp16.
// B tiles in interleaved layout: one LDS.128 = all 4 fragment words.
// ============================================================================
#define NC (NN / 32)

__global__ __launch_bounds__(256, 2) void k_attn3(
    const int* __restrict__ adj)
{
    __shared__ __align__(16) uint8_t sBH[2][FOUT * 64];   // 2 x 4 KB
    __shared__ __align__(16) uint8_t sBL[2][FOUT * 64];
    __shared__ float4 sEE[2][32];

    const int t    = threadIdx.x;
    const int wid  = t >> 5;
    const int lane = t & 31;
    const int q    = lane & 3;
    const int r    = lane >> 2;
    const int b    = blockIdx.y;
    const int i0   = blockIdx.x * 128;
    const int z    = blockIdx.z;
    const int ch0  = z * (NC / SPLIT);
    const int ch1  = ch0 + (NC / SPLIT);

    const int iA = i0 + wid * 16 + r;
    const int iB = iA + 8;
    const size_t bNN = (size_t)b * NN;

    const float2 tA = g_thR[bNN + iA];
    const float2 tB = g_thR[bNN + iB];
    const int* aA = adj + bNN * NN + (size_t)iA * NN + 2 * q;
    const int* aB = aA + 8 * NN;

    float c[8][4];
#pragma unroll
    for (int n = 0; n < 8; n++)
#pragma unroll
        for (int k = 0; k < 4; k++) c[n][k] = 0.0f;
    float laccA = 0.0f, laccB = 0.0f;

    const int feat = t >> 2;
    const int qg   = t & 3;
    const unsigned short* hhp = g_hhT + ((size_t)b * FOUT + feat) * NN + qg * 8;
    const unsigned short* hlp = g_hlT + ((size_t)b * FOUT + feat) * NN + qg * 8;
    const uint32_t sOff = (uint32_t)feat * 64 + (uint32_t)qg * 16;

    // prologue
    *(uint4*)&sBH[0][sOff] = *(const uint4*)(hhp + ch0 * 32);
    *(uint4*)&sBL[0][sOff] = *(const uint4*)(hlp + ch0 * 32);
    if (t < 32) sEE[0][t] = g_EEd[bNN + ch0 * 32 + t];

    int2 mC[8];
#pragma unroll
    for (int kk = 0; kk < 2; kk++) {
        const int jo = ch0 * 32 + kk * 16;
        mC[kk * 4 + 0] = *(const int2*)(aA + jo);
        mC[kk * 4 + 1] = *(const int2*)(aA + jo + 8);
        mC[kk * 4 + 2] = *(const int2*)(aB + jo);
        mC[kk * 4 + 3] = *(const int2*)(aB + jo + 8);
    }
    __syncthreads();

    const uint32_t tb = (uint32_t)r * 64 + (uint32_t)q * 16;

    uint4 pf_h, pf_l; float4 pf_e;
#pragma unroll 1
    for (int ch = ch0; ch < ch1; ch++) {
        const int s   = ch & 1;
        const int j0c = ch * 32;

        int2 mN[8];
        if (ch + 1 < ch1) {
            pf_h = *(const uint4*)(hhp + j0c + 32);
            pf_l = *(const uint4*)(hlp + j0c + 32);
            if (t < 32) pf_e = g_EEd[bNN + j0c + 32 + t];
#pragma unroll
            for (int kk = 0; kk < 2; kk++) {
                const int jo = j0c + 32 + kk * 16;
                mN[kk * 4 + 0] = *(const int2*)(aA + jo);
                mN[kk * 4 + 1] = *(const int2*)(aA + jo + 8);
                mN[kk * 4 + 2] = *(const int2*)(aB + jo);
                mN[kk * 4 + 3] = *(const int2*)(aB + jo + 8);
            }
        }

        // ---- A fragments from buffered adj + sEE ----
        uint32_t ah[2][4];
#pragma unroll
        for (int kk = 0; kk < 2; kk++) {
            const int jl = kk * 16 + 2 * q;
            float4 eA0 = sEE[s][jl];
            float4 eA1 = sEE[s][jl + 1];
            float4 eB0 = sEE[s][jl + 8];
            float4 eB1 = sEE[s][jl + 9];
            int2 mAa = mC[kk * 4 + 0];
            int2 mAb = mC[kk * 4 + 1];
            int2 mBa = mC[kk * 4 + 2];
            int2 mBb = mC[kk * 4 + 3];

            float pAa0 = (eA0.z >= tA.x) ? eA0.x : tA.y * eA0.y; if (mAa.x == 0) pAa0 = 0.0f;
            float pAa1 = (eA1.z >= tA.x) ? eA1.x : tA.y * eA1.y; if (mAa.y == 0) pAa1 = 0.0f;
            float pAb0 = (eB0.z >= tA.x) ? eB0.x : tA.y * eB0.y; if (mAb.x == 0) pAb0 = 0.0f;
            float pAb1 = (eB1.z >= tA.x) ? eB1.x : tA.y * eB1.y; if (mAb.y == 0) pAb1 = 0.0f;
            float pBa0 = (eA0.z >= tB.x) ? eA0.x : tB.y * eA0.y; if (mBa.x == 0) pBa0 = 0.0f;
            float pBa1 = (eA1.z >= tB.x) ? eA1.x : tB.y * eA1.y; if (mBa.y == 0) pBa1 = 0.0f;
            float pBb0 = (eB0.z >= tB.x) ? eB0.x : tB.y * eB0.y; if (mBb.x == 0) pBb0 = 0.0f;
            float pBb1 = (eB1.z >= tB.x) ? eB1.x : tB.y * eB1.y; if (mBb.y == 0) pBb1 = 0.0f;

            laccA += (pAa0 + pAa1) + (pAb0 + pAb1);
            laccB += (pBa0 + pBa1) + (pBb0 + pBb1);

            ah[kk][0] = cvt2h(pAa0, pAa1);
            ah[kk][1] = cvt2h(pBa0, pBa1);
            ah[kk][2] = cvt2h(pAb0, pAb1);
            ah[kk][3] = cvt2h(pBb0, pBb1);
        }

        // ---- mma: 8 n-tiles, one LDS.128 per (n, H/L) ----
#pragma unroll
        for (int n = 0; n < 8; n++) {
            uint4 bh = *(const uint4*)&sBH[s][(uint32_t)n * 512 + tb];
            uint4 bl = *(const uint4*)&sBL[s][(uint32_t)n * 512 + tb];
            mma16816h(c[n], ah[0], bh.x, bh.y);
            mma16816h(c[n], ah[0], bl.x, bl.y);
            mma16816h(c[n], ah[1], bh.z, bh.w);
            mma16816h(c[n], ah[1], bl.z, bl.w);
        }

        if (ch + 1 < ch1) {
            *(uint4*)&sBH[s ^ 1][sOff] = pf_h;
            *(uint4*)&sBL[s ^ 1][sOff] = pf_l;
            if (t < 32) sEE[s ^ 1][t] = pf_e;
#pragma unroll
            for (int u = 0; u < 8; u++) mC[u] = mN[u];
        }
        __syncthreads();
    }

    // ---- write split-K partials ----
    laccA += __shfl_xor_sync(0xffffffffu, laccA, 1);
    laccA += __shfl_xor_sync(0xffffffffu, laccA, 2);
    laccB += __shfl_xor_sync(0xffffffffu, laccB, 1);
    laccB += __shfl_xor_sync(0xffffffffu, laccB, 2);

    float* pa = g_pacc + (size_t)z * ((size_t)ROWS_TOT * FOUT);
    float* opA = pa + (bNN + iA) * FOUT + 2 * q;
    float* opB = pa + (bNN + iB) * FOUT + 2 * q;
#pragma unroll
    for (int n = 0; n < 8; n++) {
        *(float2*)(opA + n * 8) = make_float2(c[n][0], c[n][1]);
        *(float2*)(opB + n * 8) = make_float2(c[n][2], c[n][3]);
    }
    if (q == 0) {
        g_pl[(size_t)z * ROWS_TOT + bNN + iA] = laccA;
        g_pl[(size_t)z * ROWS_TOT + bNN + iB] = laccB;
    }
}

// ============================================================================
// Kernel 3: combine split-K partials, normalize, ELU, write output.
// ============================================================================
__global__ __launch_bounds__(256) void k_fin(float* __restrict__ out)
{
    const int idx = blockIdx.x * 256 + threadIdx.x;
    const int row = idx >> 4;
    const int fg  = (idx & 15) << 2;
    const size_t o = (size_t)row * FOUT + fg;
    const size_t PS = (size_t)ROWS_TOT * FOUT;

    float l = 0.0f;
    float4 a = make_float4(0.0f, 0.0f, 0.0f, 0.0f);
#pragma unroll
    for (int zz = 0; zz < SPLIT; zz++) {
        l += g_pl[(size_t)zz * ROWS_TOT + row];
        float4 p = *(const float4*)&g_pacc[(size_t)zz * PS + o];
        a.x += p.x; a.y += p.y; a.z += p.z; a.w += p.w;
    }
    const float li = 1.0f / l;
    float v0 = a.x * li, v1 = a.y * li, v2 = a.z * li, v3 = a.w * li;
    v0 = v0 > 0.0f ? v0 : expm1f(v0);
    v1 = v1 > 0.0f ? v1 : expm1f(v1);
    v2 = v2 > 0.0f ? v2 : expm1f(v2);
    v3 = v3 > 0.0f ? v3 : expm1f(v3);
    *(float4*)&out[o] = make_float4(v0, v1, v2, v3);
}

// ============================================================================
extern "C" void kernel_launch(void* const* d_in, const int* in_sizes, int n_in,
                              void* d_out, int out_size)
{
    const float* x     = (const float*)d_in[0];
    const int*   adj   = (const int*)d_in[1];
    const float* W     = (const float*)d_in[2];
    const float* bW    = (const float*)d_in[3];
    const float* a_src = (const float*)d_in[4];
    const float* a_dst = (const float*)d_in[5];
    const float* a_b   = (const float*)d_in[6];
    float* out = (float*)d_out;
    (void)in_sizes; (void)n_in; (void)out_size;

    cudaFuncSetAttribute(k_linear, cudaFuncAttributeMaxDynamicSharedMemorySize,
                         LIN_SMEM);

    k_linear<<<ROWS_TOT / 64, 128, LIN_SMEM>>>(x, W, bW, a_src, a_dst, a_b);

    dim3 grid(NN / 128, BB, SPLIT);
    k_attn3<<<grid, 256>>>(adj);

    k_fin<<<(ROWS_TOT * 16) / 256, 256>>>(out);
}

// round 11
// speedup vs baseline: 1.2915x; 1.1644x over previous
#include <cuda_runtime.h>
#include <cuda_fp16.h>
#include <cstdint>
#include <cstddef>

#define BB   8
#define NN   2048
#define FIN  256
#define FOUT 64
#define ALPHA 0.2f
#define SPLIT 2
#define ROWS_TOT (BB * NN)

// ---------------- scratch (device globals: allocation-free) ----------------
__device__ float2 g_thR[ROWS_TOT];                   // (-sb_i, exp((a-1)*sb_i))
__device__ float4 g_EEd[ROWS_TOT];                   // (exp(d_j), exp(a*d_j), d_j, 0)
// h transposed fp16, [b][feat][j], j stored 32-chunk INTERLEAVED:
//   pos(j) = (j&~31) + q*8 + kk*4 + half*2 + elem
__device__ unsigned short g_hhT[BB * FOUT * NN];
__device__ float g_pacc[SPLIT * ROWS_TOT * FOUT];    // 8 MB split-K partials
__device__ float g_pl[SPLIT * ROWS_TOT];

// ---------------- helpers ----------------
static __device__ __forceinline__ uint32_t cvt2h(float lo, float hi) {
    uint32_t d;
    asm("cvt.rn.f16x2.f32 %0, %1, %2;" : "=r"(d) : "f"(hi), "f"(lo));
    return d;
}
static __device__ __forceinline__ float h_lo(uint32_t w) {
    return __half2float(__ushort_as_half((unsigned short)(w & 0xffffu)));
}
static __device__ __forceinline__ float h_hi(uint32_t w) {
    return __half2float(__ushort_as_half((unsigned short)(w >> 16)));
}

static __device__ __forceinline__ void mma16816h(float* c, const uint32_t* a,
                                                 uint32_t b0, uint32_t b1) {
    asm volatile(
        "mma.sync.aligned.m16n8k16.row.col.f32.f16.f16.f32 "
        "{%0,%1,%2,%3}, {%4,%5,%6,%7}, {%8,%9}, {%0,%1,%2,%3};"
        : "+f"(c[0]), "+f"(c[1]), "+f"(c[2]), "+f"(c[3])
        : "r"(a[0]), "r"(a[1]), "r"(a[2]), "r"(a[3]), "r"(b0), "r"(b1));
}

// ============================================================================
// Kernel 1: h = x @ W + b_W via mma.sync fp16-split (3-term, table accuracy).
// 128 threads, 64 rows/CTA, grid 256. Epilogue buffer aliases W-prepack smem.
// h is stored to GMEM as single fp16 (consumed averaged; residual dropped).
// ============================================================================
#define LIN_SW_BYTES 32768
#define LIN_HB_STRIDE 68
#define LIN_SMEM (2 * LIN_SW_BYTES)

__global__ __launch_bounds__(128, 3) void k_linear(
    const float* __restrict__ x, const float* __restrict__ W,
    const float* __restrict__ bW, const float* __restrict__ a_src,
    const float* __restrict__ a_dst, const float* __restrict__ a_b)
{
    extern __shared__ __align__(16) unsigned char lsm[];
    uint32_t* WH32 = (uint32_t*)lsm;
    uint32_t* WL32 = (uint32_t*)(lsm + LIN_SW_BYTES);
    float*    hbuf = (float*)lsm;                     // alias (post-mainloop)

    const int t    = threadIdx.x;
    const int w    = t >> 5;
    const int lane = t & 31;
    const int q    = lane & 3;
    const int r    = lane >> 2;
    const int i0   = blockIdx.x * 64;
    const float ab = a_b[0];

    // ---- prepack W into fragment-order fp16 hi/lo ----
#pragma unroll
    for (int i = 0; i < 64; i++) {
        int u    = t + 128 * i;
        int half = u & 1;
        int qq   = (u >> 1) & 3;
        int n    = (u >> 3) & 63;
        int ks   = u >> 9;
        int k0   = ks * 16 + half * 8 + 2 * qq;
        float w0 = W[(size_t)k0 * FOUT + n];
        float w1 = W[(size_t)(k0 + 1) * FOUT + n];
        uint32_t hi = cvt2h(w0, w1);
        WH32[u] = hi;
        WL32[u] = cvt2h(w0 - h_lo(hi), w1 - h_hi(hi));
    }
    __syncthreads();

    const float* xA = x + (size_t)(i0 + w * 16 + r) * FIN;
    const float* xB = xA + (size_t)8 * FIN;

    float c[8][4];
#pragma unroll
    for (int n = 0; n < 8; n++)
#pragma unroll
        for (int k = 0; k < 4; k++) c[n][k] = 0.0f;

    float2 xb[2][4];
    xb[0][0] = *(const float2*)(xA + 2 * q);
    xb[0][1] = *(const float2*)(xB + 2 * q);
    xb[0][2] = *(const float2*)(xA + 8 + 2 * q);
    xb[0][3] = *(const float2*)(xB + 8 + 2 * q);

#pragma unroll
    for (int ks = 0; ks < 16; ks++) {
        const int cur = ks & 1;
        if (ks + 1 < 16) {
            const int kb = (ks + 1) * 16;
            xb[cur ^ 1][0] = *(const float2*)(xA + kb + 2 * q);
            xb[cur ^ 1][1] = *(const float2*)(xB + kb + 2 * q);
            xb[cur ^ 1][2] = *(const float2*)(xA + kb + 8 + 2 * q);
            xb[cur ^ 1][3] = *(const float2*)(xB + kb + 8 + 2 * q);
        }

        uint32_t ah[4], al[4];
#pragma unroll
        for (int e = 0; e < 4; e++) {
            float2 xv = xb[cur][e];
            ah[e] = cvt2h(xv.x, xv.y);
            al[e] = cvt2h(xv.x - h_lo(ah[e]), xv.y - h_hi(ah[e]));
        }

#pragma unroll
        for (int nt = 0; nt < 8; nt++) {
            int slot = (ks * 64 + nt * 8 + r) * 4 + q;
            uint2 bh = *(const uint2*)&WH32[slot * 2];
            uint2 bl = *(const uint2*)&WL32[slot * 2];
            mma16816h(c[nt], ah, bh.x, bh.y);
            mma16816h(c[nt], ah, bl.x, bl.y);
            mma16816h(c[nt], al, bh.x, bh.y);
        }
    }

    // ---- stash c to (aliased) smem ----
    __syncthreads();
    {
        float* hbA = hbuf + (w * 16 + r) * LIN_HB_STRIDE;
        float* hbB = hbA + 8 * LIN_HB_STRIDE;
#pragma unroll
        for (int nt = 0; nt < 8; nt++) {
            *(float2*)(hbA + nt * 8 + 2 * q) = make_float2(c[nt][0], c[nt][1]);
            *(float2*)(hbB + nt * 8 + 2 * q) = make_float2(c[nt][2], c[nt][3]);
        }
    }
    __syncthreads();

    // ---- epilogue ----
    const int fc = t & 15;
    const int rw = t >> 4;
    float4 bw4 = *(const float4*)&bW[fc * 4];
    float4 as4 = *(const float4*)&a_src[fc * 4];
    float4 ad4 = *(const float4*)&a_dst[fc * 4];

    float hv[8][4];
    float sp[8], dp[8];
#pragma unroll
    for (int e = 0; e < 8; e++) {
        float4 v = *(const float4*)&hbuf[(rw * 8 + e) * LIN_HB_STRIDE + fc * 4];
        hv[e][0] = v.x + bw4.x; hv[e][1] = v.y + bw4.y;
        hv[e][2] = v.z + bw4.z; hv[e][3] = v.w + bw4.w;
        sp[e] = hv[e][0] * as4.x + hv[e][1] * as4.y + hv[e][2] * as4.z + hv[e][3] * as4.w;
        dp[e] = hv[e][0] * ad4.x + hv[e][1] * ad4.y + hv[e][2] * ad4.z + hv[e][3] * ad4.w;
    }
#pragma unroll
    for (int o = 1; o < 16; o <<= 1) {
#pragma unroll
        for (int e = 0; e < 8; e++) {
            sp[e] += __shfl_xor_sync(0xffffffffu, sp[e], o);
            dp[e] += __shfl_xor_sync(0xffffffffu, dp[e], o);
        }
    }
    if (fc == 0) {
#pragma unroll
        for (int e = 0; e < 8; e++) {
            int row = i0 + rw * 8 + e;
            float sb = sp[e] + ab;
            g_thR[row] = make_float2(-sb, expf((ALPHA - 1.0f) * sb));
            g_EEd[row] = make_float4(expf(dp[e]), expf(ALPHA * dp[e]), dp[e], 0.0f);
        }
    }

    // ---- transposed fp16 stores, 32-chunk INTERLEAVED order ----
    const int    jb    = (i0 & (NN - 1)) + rw * 8;
    const size_t plane = (size_t)(i0 >> 11) * FOUT;
    const int    ibase = (jb & ~31) + (((jb >> 4) & 1) << 2) + (((jb >> 3) & 1) << 1);
#pragma unroll
    for (int ff = 0; ff < 4; ff++) {
        int f = fc * 4 + ff;
        size_t rowb = (plane + f) * NN + ibase;
#pragma unroll
        for (int p2 = 0; p2 < 4; p2++) {
            float v0 = hv[p2 * 2][ff], v1 = hv[p2 * 2 + 1][ff];
            *(uint32_t*)&g_hhT[rowb + p2 * 8] = cvt2h(v0, v1);
        }
    }
}

// ============================================================================
// Kernel 2: split-K masked softmax-weight P@h via mma.sync fp16.
// B single fp16, interleaved layout: one LDS.128 per n-tile.
// Grid (16, 8, SPLIT=2) x 256 threads -> single wave at 2 CTAs/SM.
// ============================================================================
#define NC (NN / 32)

__global__ __launch_bounds__(256, 2) void k_attn3(
    const int* __restrict__ adj)
{
    __shared__ __align__(16) uint8_t sBH[2][FOUT * 64];   // 2 x 4 KB
    __shared__ float4 sEE[2][32];

    const int t    = threadIdx.x;
    const int wid  = t >> 5;
    const int lane = t & 31;
    const int q    = lane & 3;
    const int r    = lane >> 2;
    const int b    = blockIdx.y;
    const int i0   = blockIdx.x * 128;
    const int z    = blockIdx.z;
    const int ch0  = z * (NC / SPLIT);
    const int ch1  = ch0 + (NC / SPLIT);

    const int iA = i0 + wid * 16 + r;
    const int iB = iA + 8;
    const size_t bNN = (size_t)b * NN;

    const float2 tA = g_thR[bNN + iA];
    const float2 tB = g_thR[bNN + iB];
    const int* aA = adj + bNN * NN + (size_t)iA * NN + 2 * q;
    const int* aB = aA + 8 * NN;

    float c[8][4];
#pragma unroll
    for (int n = 0; n < 8; n++)
#pragma unroll
        for (int k = 0; k < 4; k++) c[n][k] = 0.0f;
    float laccA = 0.0f, laccB = 0.0f;

    const int feat = t >> 2;
    const int qg   = t & 3;
    const unsigned short* hhp = g_hhT + ((size_t)b * FOUT + feat) * NN + qg * 8;
    const uint32_t sOff = (uint32_t)feat * 64 + (uint32_t)qg * 16;

    // prologue
    *(uint4*)&sBH[0][sOff] = *(const uint4*)(hhp + ch0 * 32);
    if (t < 32) sEE[0][t] = g_EEd[bNN + ch0 * 32 + t];

    int2 mC[8];
#pragma unroll
    for (int kk = 0; kk < 2; kk++) {
        const int jo = ch0 * 32 + kk * 16;
        mC[kk * 4 + 0] = *(const int2*)(aA + jo);
        mC[kk * 4 + 1] = *(const int2*)(aA + jo + 8);
        mC[kk * 4 + 2] = *(const int2*)(aB + jo);
        mC[kk * 4 + 3] = *(const int2*)(aB + jo + 8);
    }
    __syncthreads();

    const uint32_t tb = (uint32_t)r * 64 + (uint32_t)q * 16;

    uint4 pf_h; float4 pf_e;
#pragma unroll 1
    for (int ch = ch0; ch < ch1; ch++) {
        const int s   = ch & 1;
        const int j0c = ch * 32;

        int2 mN[8];
        if (ch + 1 < ch1) {
            pf_h = *(const uint4*)(hhp + j0c + 32);
            if (t < 32) pf_e = g_EEd[bNN + j0c + 32 + t];
#pragma unroll
            for (int kk = 0; kk < 2; kk++) {
                const int jo = j0c + 32 + kk * 16;
                mN[kk * 4 + 0] = *(const int2*)(aA + jo);
                mN[kk * 4 + 1] = *(const int2*)(aA + jo + 8);
                mN[kk * 4 + 2] = *(const int2*)(aB + jo);
                mN[kk * 4 + 3] = *(const int2*)(aB + jo + 8);
            }
        }

        // ---- A fragments from buffered adj + sEE ----
        uint32_t ah[2][4];
#pragma unroll
        for (int kk = 0; kk < 2; kk++) {
            const int jl = kk * 16 + 2 * q;
            float4 eA0 = sEE[s][jl];
            float4 eA1 = sEE[s][jl + 1];
            float4 eB0 = sEE[s][jl + 8];
            float4 eB1 = sEE[s][jl + 9];
            int2 mAa = mC[kk * 4 + 0];
            int2 mAb = mC[kk * 4 + 1];
            int2 mBa = mC[kk * 4 + 2];
            int2 mBb = mC[kk * 4 + 3];

            float pAa0 = (eA0.z >= tA.x) ? eA0.x : tA.y * eA0.y; if (mAa.x == 0) pAa0 = 0.0f;
            float pAa1 = (eA1.z >= tA.x) ? eA1.x : tA.y * eA1.y; if (mAa.y == 0) pAa1 = 0.0f;
            float pAb0 = (eB0.z >= tA.x) ? eB0.x : tA.y * eB0.y; if (mAb.x == 0) pAb0 = 0.0f;
            float pAb1 = (eB1.z >= tA.x) ? eB1.x : tA.y * eB1.y; if (mAb.y == 0) pAb1 = 0.0f;
            float pBa0 = (eA0.z >= tB.x) ? eA0.x : tB.y * eA0.y; if (mBa.x == 0) pBa0 = 0.0f;
            float pBa1 = (eA1.z >= tB.x) ? eA1.x : tB.y * eA1.y; if (mBa.y == 0) pBa1 = 0.0f;
            float pBb0 = (eB0.z >= tB.x) ? eB0.x : tB.y * eB0.y; if (mBb.x == 0) pBb0 = 0.0f;
            float pBb1 = (eB1.z >= tB.x) ? eB1.x : tB.y * eB1.y; if (mBb.y == 0) pBb1 = 0.0f;

            laccA += (pAa0 + pAa1) + (pAb0 + pAb1);
            laccB += (pBa0 + pBa1) + (pBb0 + pBb1);

            ah[kk][0] = cvt2h(pAa0, pAa1);
            ah[kk][1] = cvt2h(pBa0, pBa1);
            ah[kk][2] = cvt2h(pAb0, pAb1);
            ah[kk][3] = cvt2h(pBb0, pBb1);
        }

        // ---- mma: 8 n-tiles, one LDS.128 each ----
#pragma unroll
        for (int n = 0; n < 8; n++) {
            uint4 bh = *(const uint4*)&sBH[s][(uint32_t)n * 512 + tb];
            mma16816h(c[n], ah[0], bh.x, bh.y);
            mma16816h(c[n], ah[1], bh.z, bh.w);
        }

        if (ch + 1 < ch1) {
            *(uint4*)&sBH[s ^ 1][sOff] = pf_h;
            if (t < 32) sEE[s ^ 1][t] = pf_e;
#pragma unroll
            for (int u = 0; u < 8; u++) mC[u] = mN[u];
        }
        __syncthreads();
    }

    // ---- write split-K partials ----
    laccA += __shfl_xor_sync(0xffffffffu, laccA, 1);
    laccA += __shfl_xor_sync(0xffffffffu, laccA, 2);
    laccB += __shfl_xor_sync(0xffffffffu, laccB, 1);
    laccB += __shfl_xor_sync(0xffffffffu, laccB, 2);

    float* pa = g_pacc + (size_t)z * ((size_t)ROWS_TOT * FOUT);
    float* opA = pa + (bNN + iA) * FOUT + 2 * q;
    float* opB = pa + (bNN + iB) * FOUT + 2 * q;
#pragma unroll
    for (int n = 0; n < 8; n++) {
        *(float2*)(opA + n * 8) = make_float2(c[n][0], c[n][1]);
        *(float2*)(opB + n * 8) = make_float2(c[n][2], c[n][3]);
    }
    if (q == 0) {
        g_pl[(size_t)z * ROWS_TOT + bNN + iA] = laccA;
        g_pl[(size_t)z * ROWS_TOT + bNN + iB] = laccB;
    }
}

// ============================================================================
// Kernel 3: combine split-K partials, normalize, ELU, write output.
// ============================================================================
__global__ __launch_bounds__(256) void k_fin(float* __restrict__ out)
{
    const int idx = blockIdx.x * 256 + threadIdx.x;
    const int row = idx >> 4;
    const int fg  = (idx & 15) << 2;
    const size_t o = (size_t)row * FOUT + fg;
    const size_t PS = (size_t)ROWS_TOT * FOUT;

    float l = 0.0f;
    float4 a = make_float4(0.0f, 0.0f, 0.0f, 0.0f);
#pragma unroll
    for (int zz = 0; zz < SPLIT; zz++) {
        l += g_pl[(size_t)zz * ROWS_TOT + row];
        float4 p = *(const float4*)&g_pacc[(size_t)zz * PS + o];
        a.x += p.x; a.y += p.y; a.z += p.z; a.w += p.w;
    }
    const float li = 1.0f / l;
    float v0 = a.x * li, v1 = a.y * li, v2 = a.z * li, v3 = a.w * li;
    v0 = v0 > 0.0f ? v0 : expm1f(v0);
    v1 = v1 > 0.0f ? v1 : expm1f(v1);
    v2 = v2 > 0.0f ? v2 : expm1f(v2);
    v3 = v3 > 0.0f ? v3 : expm1f(v3);
    *(float4*)&out[o] = make_float4(v0, v1, v2, v3);
}

// ============================================================================
extern "C" void kernel_launch(void* const* d_in, const int* in_sizes, int n_in,
                              void* d_out, int out_size)
{
    const float* x     = (const float*)d_in[0];
    const int*   adj   = (const int*)d_in[1];
    const float* W     = (const float*)d_in[2];
    const float* bW    = (const float*)d_in[3];
    const float* a_src = (const float*)d_in[4];
    const float* a_dst = (const float*)d_in[5];
    const float* a_b   = (const float*)d_in[6];
    float* out = (float*)d_out;
    (void)in_sizes; (void)n_in; (void)out_size;

    cudaFuncSetAttribute(k_linear, cudaFuncAttributeMaxDynamicSharedMemorySize,
                         LIN_SMEM);

    k_linear<<<ROWS_TOT / 64, 128, LIN_SMEM>>>(x, W, bW, a_src, a_dst, a_b);

    dim3 grid(NN / 128, BB, SPLIT);
    k_attn3<<<grid, 256>>>(adj);

    k_fin<<<(ROWS_TOT * 16) / 256, 256>>>(out);
}